// round 15
// baseline (speedup 1.0000x reference)
#include <cuda_runtime.h>

// IoULoss: loss = mean_i ( 1 - IoU(pred_i, target_i) )   (diagonal-only, O(N))
// N = 8192 boxes, (N,4) f32 center-format [cx,cy,w,h]. Output: 1 f32 scalar.
//
// Shape: 32 CTAs x 256 threads = 8192 threads, one pair/thread, single wave.
//
// Cross-block combine: ONE u64 atomicAdd per block. The value packs
//   [63:7]  exact Q-sum  (block partial * 2^42, rounded; all non-negative)
//   [6:0]   arrival count (+1 per block; grid = 32 < 128, no carry)
// Integer addition is order-independent -> bit-deterministic. The atomic's
// return value doubles as the completion ticket: the block that sees
// (old & 127) == grid-1 is last AND holds the final total = old + own
// contribution in-register -> writes the scalar immediately. No second
// atomic, no acquire-load, no fences. Winner plain-resets the accumulator
// (kernel-completion ordering covers the next graph replay).

#define EPS 1e-7f
#define FRAC_SCALE 4398046511104.0   // 2^42

__device__ unsigned long long g_acc = 0ull;

__global__ __launch_bounds__(256, 1)
void iou_loss_kernel(const float4* __restrict__ pred,
                     const float4* __restrict__ targ,
                     float* __restrict__ out,
                     int n)
{
    const int i = blockIdx.x * blockDim.x + threadIdx.x;

    float v = 0.0f;
    if (i < n) {
        float4 a = __ldg(&pred[i]);   // cx, cy, w, h
        float4 b = __ldg(&targ[i]);

        float ax1 = a.x - a.z * 0.5f;
        float ay1 = a.y - a.w * 0.5f;
        float ax2 = a.x + a.z * 0.5f;
        float ay2 = a.y + a.w * 0.5f;

        float bx1 = b.x - b.z * 0.5f;
        float by1 = b.y - b.w * 0.5f;
        float bx2 = b.x + b.z * 0.5f;
        float by2 = b.y + b.w * 0.5f;

        float iw = fmaxf(fminf(ax2, bx2) - fmaxf(ax1, bx1), 0.0f);
        float ih = fmaxf(fminf(ay2, by2) - fmaxf(ay1, by1), 0.0f);
        float inter = iw * ih;

        float area1 = (ax2 - ax1) * (ay2 - ay1);
        float area2 = (bx2 - bx1) * (by2 - by1);
        float uni   = area1 + area2 - inter;

        v = 1.0f - inter / (uni + EPS);
    }

    // Intra-warp reduce (result needed in lane 0 only).
    #pragma unroll
    for (int off = 16; off > 0; off >>= 1)
        v += __shfl_down_sync(0xFFFFFFFFu, v, off);

    // Cross-warp reduce: warp 0 gathers the 8 warp partials and shuffles.
    __shared__ float warp_sums[8];
    const int lane = threadIdx.x & 31;
    const int wid  = threadIdx.x >> 5;
    if (lane == 0) warp_sums[wid] = v;
    __syncthreads();

    if (wid == 0) {
        float bs = (lane < 8) ? warp_sums[lane] : 0.0f;
        #pragma unroll
        for (int off = 4; off > 0; off >>= 1)
            bs += __shfl_down_sync(0xFFFFFFFFu, bs, off);

        if (lane == 0) {
            // Pack exact Q42 partial + arrival count into one atomic.
            unsigned long long q = (unsigned long long)llrint((double)bs * FRAC_SCALE);
            unsigned long long contrib = (q << 7) | 1ull;
            unsigned long long old = atomicAdd(&g_acc, contrib);

            if ((old & 127ull) == (unsigned long long)(gridDim.x - 1)) {
                // Last block: final total already in-register.
                unsigned long long total = old + contrib;
                double s = (double)(total >> 7) / FRAC_SCALE;
                out[0] = (float)(s / (double)n);
                g_acc = 0ull;   // reset for next graph replay
            }
        }
    }
}

extern "C" void kernel_launch(void* const* d_in, const int* in_sizes, int n_in,
                              void* d_out, int out_size)
{
    const float4* pred = (const float4*)d_in[0];
    const float4* targ = (const float4*)d_in[1];
    float* out = (float*)d_out;

    int n = in_sizes[0] / 4;                     // 8192 boxes
    int blocks = (n + 255) / 256;                // 32

    iou_loss_kernel<<<blocks, 256>>>(pred, targ, out, n);
}